// round 5
// baseline (speedup 1.0000x reference)
#include <cuda_runtime.h>
#include <cuda_bf16.h>

// Single fused kernel, 512 threads, fully warp-private presence+loss:
// warp w owns batch w for BOTH sampling and loss, so the class-presence mask
// lives in registers (every lane, via __reduce_or_sync) and never touches
// shared memory. No block-wide coordination except ONE __syncthreads before
// the final 16-partial reduction.
//
// Presence decided from a 512-element sampled prefix (32 lanes x 4 int4).
// If the sampled mask is full, remaining labels provably cannot change the
// (monotone) OR; miss prob ~2e-11/batch on uniform labels. An unsaturated
// warp scans its own batch alone (chunked, warp-uniform early exit) --
// correct for arbitrary inputs, no cross-warp protocol. Decision depends
// only on input data: same inputs -> same work -> same output.

__global__ void fused_segenc_loss_kernel(const float* __restrict__ preds,
                                         const int*   __restrict__ targets,
                                         float* __restrict__ out,
                                         int B, int C, int n_per_batch) {
    __shared__ float warp_sums[32];

    const int t      = threadIdx.x;
    const int w      = t >> 5;
    const int lane   = t & 31;
    const int nwarps = blockDim.x >> 5;
    const unsigned int full_mask = (1u << C) - 1u;
    const bool vec_ok = ((n_per_batch & 3) == 0);
    const int total4  = n_per_batch >> 2;
    const int n = B * C;

    float acc = 0.0f;

    // Warp w handles batches w, w+nwarps, ... (single iteration when B<=16).
    for (int bb = w; bb < B; bb += nwarps) {
        // ---- issue preds load early (tiny, overlaps everything)
        float x = 0.0f;
        if (lane < C) x = preds[bb * C + lane];

        // ---- sample loads: 32 lanes x 4 int4 = 512 ints, coalesced prefix
        unsigned int m = 0u;
        if (vec_ok) {
            const int4* __restrict__ t4 =
                reinterpret_cast<const int4*>(targets) + (long long)bb * total4;
            const int limit = min(128, total4);
            #pragma unroll
            for (int k = 0; k < 4; k++) {
                const int idx = lane + (k << 5);
                if (idx < limit) {
                    const int4 v = t4[idx];
                    m |= (1u << (v.x & 31)) | (1u << (v.y & 31)) |
                         (1u << (v.z & 31)) | (1u << (v.w & 31));
                }
            }
        }

        // ---- transcendentals while target loads are in flight
        const float l   = log1pf(expf(-fabsf(x)));  // = -logsig(|x|)
        const float lsp = fminf(x, 0.0f) - l;       // logsig(x)
        const float lsn = fminf(-x, 0.0f) - l;      // logsig(-x)

        // ---- warp-register mask (all lanes get it)
        unsigned int wm = __reduce_or_sync(0xffffffffu, m);

        // ---- rare fallback: this warp scans its own batch, chunked with
        //      warp-uniform early exit (wm identical across lanes).
        if ((wm & full_mask) != full_mask) {
            const int* __restrict__ tb = targets + (long long)bb * n_per_batch;
            for (int base = 0; base < n_per_batch; base += 4096) {
                const int end = min(base + 4096, n_per_batch);
                unsigned int mm = 0u;
                for (int i = base + lane; i < end; i += 32)
                    mm |= 1u << (tb[i] & 31);
                wm |= __reduce_or_sync(0xffffffffu, mm);
                if ((wm & full_mask) == full_mask) break;
            }
        }

        // ---- loss terms for this batch (lanes 0..C-1), mask in-register
        if (lane < C) acc += -(((wm >> lane) & 1u) ? lsp : lsn);
    }

    // ---- warp-local sum, then one barrier and a 16-way final reduction
    for (int off = 16; off > 0; off >>= 1)
        acc += __shfl_down_sync(0xffffffffu, acc, off);
    if (lane == 0) warp_sums[w] = acc;
    __syncthreads();
    if (t < 32) {
        float v = (t < nwarps) ? warp_sums[t] : 0.0f;
        for (int off = 16; off > 0; off >>= 1)
            v += __shfl_down_sync(0xffffffffu, v, off);
        if (t == 0) out[0] = v / (float)n;
    }
}

extern "C" void kernel_launch(void* const* d_in, const int* in_sizes, int n_in,
                              void* d_out, int out_size) {
    const float* preds   = (const float*)d_in[0];
    const int*   targets = (const int*)d_in[1];

    const int C = 19;                       // NUM_CLASSES (fixed by problem)
    const int B = in_sizes[0] / C;          // 16
    const int n_per_batch = in_sizes[1] / B;

    fused_segenc_loss_kernel<<<1, 512>>>(preds, targets, (float*)d_out,
                                         B, C, n_per_batch);
}